// round 4
// baseline (speedup 1.0000x reference)
#include <cuda_runtime.h>
#include <cstdint>
typedef unsigned long long ull;

__device__ float g_xp[(size_t)1024 * 512 * 512];  // 1 GiB gate preacts
__device__ float g_h1[(size_t)1024 * 512 * 128];  // 256 MB layer-0 h seq
__device__ float g_h2[1024 * 128];

__device__ __forceinline__ ull pk2(float a, float b) { ull r; asm("mov.b64 %0,{%1,%2};" : "=l"(r) : "f"(a), "f"(b)); return r; }
__device__ __forceinline__ void upk2(ull p, float& a, float& b) { asm("mov.b64 {%0,%1},%2;" : "=f"(a), "=f"(b) : "l"(p)); }
__device__ __forceinline__ void fma2(ull& d, ull a, ull b) { asm("fma.rn.f32x2 %0,%1,%2,%0;" : "+l"(d) : "l"(a), "l"(b)); }
__device__ __forceinline__ float ex2f_(float x) { float r; asm("ex2.approx.f32 %0,%1;" : "=f"(r) : "f"(x)); return r; }
__device__ __forceinline__ float rcpf_(float x) { float r; asm("rcp.approx.f32 %0,%1;" : "=f"(r) : "f"(x)); return r; }
__device__ __forceinline__ float sigf(float x) { return rcpf_(1.f + ex2f_(-1.44269504f * x)); }
__device__ __forceinline__ float tanhf_(float x) { return fmaf(2.f, rcpf_(1.f + ex2f_(-2.88539009f * x)), -1.f); }

// ---- x-projection GEMM: out[row*512 + u*4 + q] = in[row] . W[q*128+u] + b ----
// 128 rows x 128 gate-cols per CTA; thread = (gg 16) x (rg 16), 8 rows each.
template <int K>
__global__ void __launch_bounds__(256)
k_xproj(const float* __restrict__ in, const float* __restrict__ W,
        const float* __restrict__ bi, const float* __restrict__ bh,
        float* __restrict__ outp)
{
    extern __shared__ float sm[];
    float* in_s = sm;             // [K][132] rows transposed
    float* w_s = sm + K * 132;    // [K][132] gate cols j = u_local*4+q
    const int tid = threadIdx.x, row0 = blockIdx.x * 128, gt = blockIdx.y;

    for (int i = tid; i < 128 * K; i += 256) {
        int r = i / K, k = i % K;
        in_s[k * 132 + r] = in[(size_t)(row0 + r) * K + k];
    }
    for (int i = tid; i < 128 * K; i += 256) {
        int j = i / K, k = i % K;
        int g = (j & 3) * 128 + gt * 32 + (j >> 2);
        w_s[k * 132 + j] = W[(size_t)g * K + k];
    }
    __syncthreads();

    const int gg = tid & 15, rg = tid >> 4;
    ull acc[8][4];
#pragma unroll
    for (int r = 0; r < 8; r++)
#pragma unroll
        for (int p = 0; p < 4; p++) acc[r][p] = 0ULL;

    const ulonglong2* wv = (const ulonglong2*)w_s;   // stride 33 per k
    const float4* is4 = (const float4*)in_s;         // stride 33 per k

#pragma unroll 4
    for (int k = 0; k < K; ++k) {
        ulonglong2 wA = wv[k * 33 + gg * 2];
        ulonglong2 wB = wv[k * 33 + gg * 2 + 1];
        float4 vA = is4[k * 33 + rg * 2];
        float4 vB = is4[k * 33 + rg * 2 + 1];
        ull a[8];
        a[0] = pk2(vA.x, vA.x); a[1] = pk2(vA.y, vA.y);
        a[2] = pk2(vA.z, vA.z); a[3] = pk2(vA.w, vA.w);
        a[4] = pk2(vB.x, vB.x); a[5] = pk2(vB.y, vB.y);
        a[6] = pk2(vB.z, vB.z); a[7] = pk2(vB.w, vB.w);
#pragma unroll
        for (int r = 0; r < 8; r++) {
            fma2(acc[r][0], wA.x, a[r]); fma2(acc[r][1], wA.y, a[r]);
            fma2(acc[r][2], wB.x, a[r]); fma2(acc[r][3], wB.y, a[r]);
        }
    }

    const int j0 = gg * 8;
    float bs[8];
#pragma unroll
    for (int jj = 0; jj < 8; jj++) {
        int j = j0 + jj, g = (j & 3) * 128 + gt * 32 + (j >> 2);
        bs[jj] = bi[g] + bh[g];
    }
#pragma unroll
    for (int r = 0; r < 8; r++) {
        float v[8];
        upk2(acc[r][0], v[0], v[1]); upk2(acc[r][1], v[2], v[3]);
        upk2(acc[r][2], v[4], v[5]); upk2(acc[r][3], v[6], v[7]);
        size_t base = (size_t)(row0 + rg * 8 + r) * 512 + gt * 128 + j0;
        *(float4*)&outp[base] = make_float4(v[0] + bs[0], v[1] + bs[1], v[2] + bs[2], v[3] + bs[3]);
        *(float4*)&outp[base + 4] = make_float4(v[4] + bs[4], v[5] + bs[5], v[6] + bs[6], v[7] + bs[7]);
    }
}

// ---- recurrence: 2-CTA cluster, 64 units/CTA, 16 batch rows/cluster ----
// h stored ONCE (no duplication): hb[buf][unit k][row 0..15], stride STR.
#define STR 20
#define HBUFF (128 * STR)
#define REC_SMEM (128 * 256 * 4 + 2 * HBUFF * 4)

__global__ void __cluster_dims__(2, 1, 1) __launch_bounds__(256, 1)
k_recur(const float* __restrict__ Whh, const float* __restrict__ xp,
        float* __restrict__ hseq, float* __restrict__ hlast, int store_all)
{
    extern __shared__ float sm[];
    float* Wsm = sm;              // [128 k][256] = u*4+q
    float* hb = sm + 128 * 256;   // [2][128][STR]

    const int tid = threadIdx.x;
    const int rank = blockIdx.x & 1, peer = rank ^ 1, cl = blockIdx.x >> 1;
    const int u_l = tid >> 2, bg = tid & 3;
    const int ug = rank * 64 + u_l;
    const int b0 = cl * 16 + bg * 4;

    for (int i = tid; i < 256 * 128; i += 256) {
        int row = i >> 7, k = i & 127;
        Wsm[k * 256 + row] = Whh[(size_t)((row & 3) * 128 + rank * 64 + (row >> 2)) * 128 + k];
    }
    for (int i = tid; i < 2 * HBUFF; i += 256) hb[i] = 0.f;

    uint32_t pbase;
    {
        uint32_t lb = (uint32_t)__cvta_generic_to_shared(hb);
        asm("mapa.shared::cluster.u32 %0,%1,%2;" : "=r"(pbase) : "r"(lb), "r"(peer));
    }
    asm volatile("barrier.cluster.arrive;\n\tbarrier.cluster.wait;" ::: "memory");

    const ulonglong2* wv = (const ulonglong2*)Wsm;   // k*64 + u_l
    const ulonglong2* xpv = (const ulonglong2*)xp;

    float c[4] = {0.f, 0.f, 0.f, 0.f};
    ulonglong2 pf[4];
#pragma unroll
    for (int j = 0; j < 4; j++) pf[j] = xpv[(size_t)(b0 + j) * 512 * 128 + ug];

    for (int t = 0; t < 512; ++t) {
        const float* hr = hb + (t & 1) * HBUFF;
        float* hw = hb + ((t & 1) ^ 1) * HBUFF;
        const uint32_t pw0 = pbase + ((t & 1) ^ 1) * HBUFF * 4;

        // init accumulators batch-pair-packed: A_g[pair] = (gate_g row j, row j+1)
        float xi[4], xf[4], xg[4], xo[4];
#pragma unroll
        for (int j = 0; j < 4; j++) { upk2(pf[j].x, xi[j], xf[j]); upk2(pf[j].y, xg[j], xo[j]); }
        ull Ai01 = pk2(xi[0], xi[1]), Ai23 = pk2(xi[2], xi[3]);
        ull Af01 = pk2(xf[0], xf[1]), Af23 = pk2(xf[2], xf[3]);
        ull Ag01 = pk2(xg[0], xg[1]), Ag23 = pk2(xg[2], xg[3]);
        ull Ao01 = pk2(xo[0], xo[1]), Ao23 = pk2(xo[2], xo[3]);

        if (t + 1 < 512) {
#pragma unroll
            for (int j = 0; j < 4; j++)
                pf[j] = xpv[((size_t)(b0 + j) * 512 + t + 1) * 128 + ug];
        }

#pragma unroll 4
        for (int k = 0; k < 128; ++k) {
            ulonglong2 w = wv[k * 64 + u_l];
            float wi, wf, wg, wo;
            upk2(w.x, wi, wf); upk2(w.y, wg, wo);
            ull wii = pk2(wi, wi), wff = pk2(wf, wf), wgg = pk2(wg, wg), woo = pk2(wo, wo);
            ulonglong2 h4 = *(const ulonglong2*)&hr[k * STR + bg * 4];
            fma2(Ai01, wii, h4.x); fma2(Ai23, wii, h4.y);
            fma2(Af01, wff, h4.x); fma2(Af23, wff, h4.y);
            fma2(Ag01, wgg, h4.x); fma2(Ag23, wgg, h4.y);
            fma2(Ao01, woo, h4.x); fma2(Ao23, woo, h4.y);
        }

        float gi[4], gf[4], gc[4], go[4], hv[4];
        upk2(Ai01, gi[0], gi[1]); upk2(Ai23, gi[2], gi[3]);
        upk2(Af01, gf[0], gf[1]); upk2(Af23, gf[2], gf[3]);
        upk2(Ag01, gc[0], gc[1]); upk2(Ag23, gc[2], gc[3]);
        upk2(Ao01, go[0], go[1]); upk2(Ao23, go[2], go[3]);
#pragma unroll
        for (int j = 0; j < 4; j++) {
            float ii = sigf(gi[j]), ff = sigf(gf[j]), gz = tanhf_(gc[j]), oo = sigf(go[j]);
            c[j] = ff * c[j] + ii * gz;
            hv[j] = oo * tanhf_(c[j]);
        }

        const int idx = ug * STR + bg * 4;
        *(float4*)&hw[idx] = make_float4(hv[0], hv[1], hv[2], hv[3]);
        {
            ull p01 = pk2(hv[0], hv[1]), p23 = pk2(hv[2], hv[3]);
            uint32_t pa = pw0 + idx * 4;
            asm volatile("st.shared::cluster.u64 [%0],%1;" :: "r"(pa), "l"(p01) : "memory");
            asm volatile("st.shared::cluster.u64 [%0+8],%1;" :: "r"(pa), "l"(p23) : "memory");
        }

        if (store_all) {
#pragma unroll
            for (int j = 0; j < 4; j++)
                hseq[((size_t)(b0 + j) * 512 + t) * 128 + ug] = hv[j];
        } else if (t == 511) {
#pragma unroll
            for (int j = 0; j < 4; j++)
                hlast[(size_t)(b0 + j) * 128 + ug] = hv[j];
        }
        asm volatile("barrier.cluster.arrive;\n\tbarrier.cluster.wait;" ::: "memory");
    }
}

// ---- head MLP ----
__global__ void __launch_bounds__(128)
k_head(const float* __restrict__ h2, const float* __restrict__ f1w,
       const float* __restrict__ f1b, const float* __restrict__ f2w,
       const float* __restrict__ f2b, float* __restrict__ out)
{
    __shared__ float w1[64 * 128], w2[64], b1[64];
    const int tid = threadIdx.x;
    for (int i = tid; i < 64 * 128; i += 128) w1[i] = f1w[i];
    if (tid < 64) { w2[tid] = f2w[tid]; b1[tid] = f1b[tid]; }
    __syncthreads();
    const int b = blockIdx.x * 128 + tid;
    float hreg[128];
#pragma unroll
    for (int k = 0; k < 128; k++) hreg[k] = h2[(size_t)b * 128 + k];
    float acc = f2b[0];
    for (int j = 0; j < 64; j++) {
        float a = b1[j];
#pragma unroll
        for (int k = 0; k < 128; k++) a = fmaf(w1[j * 128 + k], hreg[k], a);
        acc = fmaf(w2[j], fmaxf(a, 0.f), acc);
    }
    out[b] = acc;
}

extern "C" void kernel_launch(void* const* d_in, const int* in_sizes, int n_in,
                              void* d_out, int out_size)
{
    const float* x = (const float*)d_in[0];
    const float* Wih0 = (const float*)d_in[1];
    const float* Whh0 = (const float*)d_in[2];
    const float* bih0 = (const float*)d_in[3];
    const float* bhh0 = (const float*)d_in[4];
    const float* Wih1 = (const float*)d_in[5];
    const float* Whh1 = (const float*)d_in[6];
    const float* bih1 = (const float*)d_in[7];
    const float* bhh1 = (const float*)d_in[8];
    const float* f1w = (const float*)d_in[9];
    const float* f1b = (const float*)d_in[10];
    const float* f2w = (const float*)d_in[11];
    const float* f2b = (const float*)d_in[12];
    float* out = (float*)d_out;

    float *xp, *h1, *h2;
    cudaGetSymbolAddress((void**)&xp, g_xp);
    cudaGetSymbolAddress((void**)&h1, g_h1);
    cudaGetSymbolAddress((void**)&h2, g_h2);

    const int smA = 2 * 64 * 132 * 4;    // 67.6 KB
    const int smC = 2 * 128 * 132 * 4;   // 135 KB
    cudaFuncSetAttribute((const void*)k_xproj<64>, cudaFuncAttributeMaxDynamicSharedMemorySize, smA);
    cudaFuncSetAttribute((const void*)k_xproj<128>, cudaFuncAttributeMaxDynamicSharedMemorySize, smC);
    cudaFuncSetAttribute((const void*)k_recur, cudaFuncAttributeMaxDynamicSharedMemorySize, REC_SMEM);

    dim3 gA(4096, 4);
    k_xproj<64><<<gA, 256, smA>>>(x, Wih0, bih0, bhh0, xp);
    k_recur<<<128, 256, REC_SMEM>>>(Whh0, xp, h1, h2, 1);
    k_xproj<128><<<gA, 256, smC>>>(h1, Wih1, bih1, bhh1, xp);
    k_recur<<<128, 256, REC_SMEM>>>(Whh1, xp, h1, h2, 0);
    k_head<<<8, 128>>>(h2, f1w, f1b, f2w, f2b, out);
}

// round 6
// speedup vs baseline: 1.0398x; 1.0398x over previous
#include <cuda_runtime.h>
#include <cstdint>
typedef unsigned long long ull;

__device__ float g_xp[(size_t)1024 * 512 * 512];  // 1 GiB gate preacts
__device__ float g_h1[(size_t)1024 * 512 * 128];  // 256 MB layer-0 h seq
__device__ float g_h2[1024 * 128];

__device__ __forceinline__ ull pk2(float a, float b) { ull r; asm("mov.b64 %0,{%1,%2};" : "=l"(r) : "f"(a), "f"(b)); return r; }
__device__ __forceinline__ void upk2(ull p, float& a, float& b) { asm("mov.b64 {%0,%1},%2;" : "=f"(a), "=f"(b) : "l"(p)); }
__device__ __forceinline__ void fma2(ull& d, ull a, ull b) { asm("fma.rn.f32x2 %0,%1,%2,%0;" : "+l"(d) : "l"(a), "l"(b)); }
__device__ __forceinline__ float ex2f_(float x) { float r; asm("ex2.approx.f32 %0,%1;" : "=f"(r) : "f"(x)); return r; }
__device__ __forceinline__ float rcpf_(float x) { float r; asm("rcp.approx.f32 %0,%1;" : "=f"(r) : "f"(x)); return r; }
__device__ __forceinline__ float sigf(float x) { return rcpf_(1.f + ex2f_(-1.44269504f * x)); }
__device__ __forceinline__ float tanhf_(float x) { return fmaf(2.f, rcpf_(1.f + ex2f_(-2.88539009f * x)), -1.f); }

// ---- x-projection GEMM (R3 layout: 64-row tile, 2 CTAs/SM) ----
// out[row*512 + u*4 + q] = in[row] . W[q*128+u] + b
template <int K>
__global__ void __launch_bounds__(256)
k_xproj(const float* __restrict__ in, const float* __restrict__ W,
        const float* __restrict__ bi, const float* __restrict__ bh,
        float* __restrict__ outp)
{
    extern __shared__ float sm[];
    float* in_s = sm;             // [K][68]
    float* w_s = sm + K * 68;     // [K][132]
    const int tid = threadIdx.x, row0 = blockIdx.x * 64, gt = blockIdx.y;

    for (int i = tid; i < 64 * K; i += 256) {
        int r = i / K, k = i % K;
        in_s[k * 68 + r] = in[(size_t)(row0 + r) * K + k];
    }
    for (int i = tid; i < 128 * K; i += 256) {
        int j = i / K, k = i % K;
        int g = (j & 3) * 128 + gt * 32 + (j >> 2);
        w_s[k * 132 + j] = W[(size_t)g * K + k];
    }
    __syncthreads();

    const int gg = tid & 15, rg = tid >> 4;
    ull acc[4][4];
#pragma unroll
    for (int r = 0; r < 4; r++)
#pragma unroll
        for (int p = 0; p < 4; p++) acc[r][p] = 0ULL;

    const ulonglong2* wv = (const ulonglong2*)w_s;
    const float4* is4 = (const float4*)in_s;
#pragma unroll 4
    for (int k = 0; k < K; ++k) {
        ulonglong2 wA = wv[k * 33 + gg * 2];
        ulonglong2 wB = wv[k * 33 + gg * 2 + 1];
        float4 av = is4[k * 17 + rg];
        ull a0 = pk2(av.x, av.x), a1 = pk2(av.y, av.y);
        ull a2 = pk2(av.z, av.z), a3 = pk2(av.w, av.w);
        fma2(acc[0][0], wA.x, a0); fma2(acc[0][1], wA.y, a0); fma2(acc[0][2], wB.x, a0); fma2(acc[0][3], wB.y, a0);
        fma2(acc[1][0], wA.x, a1); fma2(acc[1][1], wA.y, a1); fma2(acc[1][2], wB.x, a1); fma2(acc[1][3], wB.y, a1);
        fma2(acc[2][0], wA.x, a2); fma2(acc[2][1], wA.y, a2); fma2(acc[2][2], wB.x, a2); fma2(acc[2][3], wB.y, a2);
        fma2(acc[3][0], wA.x, a3); fma2(acc[3][1], wA.y, a3); fma2(acc[3][2], wB.x, a3); fma2(acc[3][3], wB.y, a3);
    }

    const int j0 = gg * 8;
    float bs[8];
#pragma unroll
    for (int jj = 0; jj < 8; jj++) {
        int j = j0 + jj, g = (j & 3) * 128 + gt * 32 + (j >> 2);
        bs[jj] = bi[g] + bh[g];
    }
#pragma unroll
    for (int r = 0; r < 4; r++) {
        float v[8];
        upk2(acc[r][0], v[0], v[1]); upk2(acc[r][1], v[2], v[3]);
        upk2(acc[r][2], v[4], v[5]); upk2(acc[r][3], v[6], v[7]);
        size_t base = (size_t)(row0 + rg * 4 + r) * 512 + gt * 128 + j0;
        *(float4*)&outp[base] = make_float4(v[0] + bs[0], v[1] + bs[1], v[2] + bs[2], v[3] + bs[3]);
        *(float4*)&outp[base + 4] = make_float4(v[4] + bs[4], v[5] + bs[5], v[6] + bs[6], v[7] + bs[7]);
    }
}

// ---- recurrence: 2-CTA cluster, 512 threads/CTA, 64 units/CTA, 16 rows/cluster
// h stored duplicated (h,h): hb[buf][k unit 0..127][row 0..15] as ull, 128B/k.
#define HD (128 * 16)                       // ull per h buffer
#define REC_SMEM (128 * 256 * 4 + 2 * HD * 8)

__global__ void __cluster_dims__(2, 1, 1) __launch_bounds__(512, 1)
k_recur(const float* __restrict__ Whh, const float* __restrict__ xp,
        float* __restrict__ hseq, float* __restrict__ hlast, int store_all)
{
    extern __shared__ float sm[];
    float* Wsm = sm;                        // [128 k][256] = u*4+q
    ull* hb = (ull*)(sm + 128 * 256);       // [2][128][16] (h,h) pairs

    const int tid = threadIdx.x;
    const int rank = blockIdx.x & 1, peer = rank ^ 1, cl = blockIdx.x >> 1;
    const int u_l = tid >> 3, bg = tid & 7;     // 64 units x 8 row-groups
    const int ug = rank * 64 + u_l;
    const int b0 = cl * 16 + bg * 2;            // 2 rows per thread

    for (int i = tid; i < 256 * 128; i += 512) {
        int row = i >> 7, k = i & 127;
        Wsm[k * 256 + row] = Whh[(size_t)((row & 3) * 128 + rank * 64 + (row >> 2)) * 128 + k];
    }
    for (int i = tid; i < 2 * HD; i += 512) hb[i] = 0ULL;

    uint32_t pbase;
    {
        uint32_t lb = (uint32_t)__cvta_generic_to_shared(hb);
        asm("mapa.shared::cluster.u32 %0,%1,%2;" : "=r"(pbase) : "r"(lb), "r"(peer));
    }
    asm volatile("barrier.cluster.arrive.aligned;\n\tbarrier.cluster.wait.aligned;" ::: "memory");

    const ulonglong2* wv = (const ulonglong2*)Wsm;   // k*64 + u_l
    const ulonglong2* xpv = (const ulonglong2*)xp;

    float c0 = 0.f, c1 = 0.f;
    ulonglong2 pf0 = xpv[(size_t)b0 * 512 * 128 + ug];
    ulonglong2 pf1 = xpv[(size_t)(b0 + 1) * 512 * 128 + ug];

    for (int t = 0; t < 512; ++t) {
        const ull* hr = hb + (t & 1) * HD;
        ull* hw = hb + ((t & 1) ^ 1) * HD;
        const uint32_t pw0 = pbase + (((t & 1) ^ 1) * HD) * 8;

        ull Aif0 = pf0.x, Ago0 = pf0.y;   // (i,f) and (g,o) pair accumulators
        ull Aif1 = pf1.x, Ago1 = pf1.y;
        if (t + 1 < 512) {
            pf0 = xpv[((size_t)b0 * 512 + t + 1) * 128 + ug];
            pf1 = xpv[((size_t)(b0 + 1) * 512 + t + 1) * 128 + ug];
        }

#pragma unroll 8
        for (int k = 0; k < 128; ++k) {
            ulonglong2 w = wv[k * 64 + u_l];                       // (wi,wf),(wg,wo)
            ulonglong2 h2 = *(const ulonglong2*)&hr[k * 16 + bg * 2]; // (h0,h0),(h1,h1)
            fma2(Aif0, w.x, h2.x); fma2(Ago0, w.y, h2.x);
            fma2(Aif1, w.x, h2.y); fma2(Ago1, w.y, h2.y);
        }

        float hv0, hv1;
        {
            float gi, gf, gc, go;
            upk2(Aif0, gi, gf); upk2(Ago0, gc, go);
            float ii = sigf(gi), ff = sigf(gf), gz = tanhf_(gc), oo = sigf(go);
            c0 = ff * c0 + ii * gz;  hv0 = oo * tanhf_(c0);
            upk2(Aif1, gi, gf); upk2(Ago1, gc, go);
            ii = sigf(gi); ff = sigf(gf); gz = tanhf_(gc); oo = sigf(go);
            c1 = ff * c1 + ii * gz;  hv1 = oo * tanhf_(c1);
        }

        const int idx = ug * 16 + bg * 2;
        ull p0 = pk2(hv0, hv0), p1 = pk2(hv1, hv1);
        *(ulonglong2*)&hw[idx] = make_ulonglong2(p0, p1);
        {
            uint32_t pa = pw0 + idx * 8;
            asm volatile("st.shared::cluster.u64 [%0],%1;" :: "r"(pa), "l"(p0) : "memory");
            asm volatile("st.shared::cluster.u64 [%0+8],%1;" :: "r"(pa), "l"(p1) : "memory");
        }

        if (store_all) {
            hseq[((size_t)b0 * 512 + t) * 128 + ug] = hv0;
            hseq[((size_t)(b0 + 1) * 512 + t) * 128 + ug] = hv1;
        } else if (t == 511) {
            hlast[(size_t)b0 * 128 + ug] = hv0;
            hlast[(size_t)(b0 + 1) * 128 + ug] = hv1;
        }
        asm volatile("barrier.cluster.arrive.aligned;\n\tbarrier.cluster.wait.aligned;" ::: "memory");
    }
}

// ---- head MLP ----
__global__ void __launch_bounds__(128)
k_head(const float* __restrict__ h2, const float* __restrict__ f1w,
       const float* __restrict__ f1b, const float* __restrict__ f2w,
       const float* __restrict__ f2b, float* __restrict__ out)
{
    __shared__ float w1[64 * 128], w2[64], b1[64];
    const int tid = threadIdx.x;
    for (int i = tid; i < 64 * 128; i += 128) w1[i] = f1w[i];
    if (tid < 64) { w2[tid] = f2w[tid]; b1[tid] = f1b[tid]; }
    __syncthreads();
    const int b = blockIdx.x * 128 + tid;
    float hreg[128];
#pragma unroll
    for (int k = 0; k < 128; k++) hreg[k] = h2[(size_t)b * 128 + k];
    float acc = f2b[0];
    for (int j = 0; j < 64; j++) {
        float a = b1[j];
#pragma unroll
        for (int k = 0; k < 128; k++) a = fmaf(w1[j * 128 + k], hreg[k], a);
        acc = fmaf(w2[j], fmaxf(a, 0.f), acc);
    }
    out[b] = acc;
}

extern "C" void kernel_launch(void* const* d_in, const int* in_sizes, int n_in,
                              void* d_out, int out_size)
{
    const float* x = (const float*)d_in[0];
    const float* Wih0 = (const float*)d_in[1];
    const float* Whh0 = (const float*)d_in[2];
    const float* bih0 = (const float*)d_in[3];
    const float* bhh0 = (const float*)d_in[4];
    const float* Wih1 = (const float*)d_in[5];
    const float* Whh1 = (const float*)d_in[6];
    const float* bih1 = (const float*)d_in[7];
    const float* bhh1 = (const float*)d_in[8];
    const float* f1w = (const float*)d_in[9];
    const float* f1b = (const float*)d_in[10];
    const float* f2w = (const float*)d_in[11];
    const float* f2b = (const float*)d_in[12];
    float* out = (float*)d_out;

    float *xp, *h1, *h2;
    cudaGetSymbolAddress((void**)&xp, g_xp);
    cudaGetSymbolAddress((void**)&h1, g_h1);
    cudaGetSymbolAddress((void**)&h2, g_h2);

    const int smA = (64 * 68 + 64 * 132) * 4;    // 51.2 KB -> 2 CTAs/SM
    const int smC = (128 * 68 + 128 * 132) * 4;  // 102.4 KB -> 2 CTAs/SM
    cudaFuncSetAttribute((const void*)k_xproj<64>, cudaFuncAttributeMaxDynamicSharedMemorySize, smA);
    cudaFuncSetAttribute((const void*)k_xproj<128>, cudaFuncAttributeMaxDynamicSharedMemorySize, smC);
    cudaFuncSetAttribute((const void*)k_recur, cudaFuncAttributeMaxDynamicSharedMemorySize, REC_SMEM);

    dim3 gA(8192, 4);
    k_xproj<64><<<gA, 256, smA>>>(x, Wih0, bih0, bhh0, xp);
    k_recur<<<128, 512, REC_SMEM>>>(Whh0, xp, h1, h2, 1);
    k_xproj<128><<<gA, 256, smC>>>(h1, Wih1, bih1, bhh1, xp);
    k_recur<<<128, 512, REC_SMEM>>>(Whh1, xp, h1, h2, 0);
    k_head<<<8, 128>>>(h2, f1w, f1b, f2w, f2b, out);
}